// round 16
// baseline (speedup 1.0000x reference)
#include <cuda_runtime.h>
#include <cstddef>

#define B_   8
#define T_   512
#define K_   8
#define H_   128
#define G3_  384
#define DIN_ 100
#define DG_  50
#define NL_  20

// device scratch (no allocation allowed)
__device__ __align__(16) float g_xW  [B_*T_*G3_];
__device__ __align__(16) float g_xWa [B_*T_*H_];
__device__ __align__(16) float g_gW  [B_*T_*K_*G3_];
__device__ __align__(16) float g_WwP [32*G3_*4];   // Ww_hh packed [d/4][g][4]
__device__ __align__(16) float g_WaP [32*H_*4];    // Wa_hh packed [d/4][h][4]
__device__ __align__(16) float g_Wt2 [NL_*H_];     // W_tag[:, :128] + W_tag[:, 128:]
__device__ __align__(16) float g_WihT [DIN_*G3_];
__device__ __align__(16) float g_WaihT[DIN_*H_];
__device__ __align__(16) float g_WwihT[DG_*G3_];
__device__ __align__(16) float g_hout[B_*T_*H_];   // h history for tag post-pass

// smem layout (float offsets); helper reuses O_HR as its h mirror
#define O_SW    0
#define O_VH    49152
#define O_HR    52224
#define O_CR    53248
#define O_IS    54272
#define O_OS    54400
#define O_GT    54528
#define O_CW    54656
#define O_PART  55680
#define O_INT   56704
#define O_MBAR  56736      // mbar0 (vh, count 12) @ +0 ; mbar1 (h, count 4) @ +8B
#define REC_SMEM ((56740) * 4)

__device__ __forceinline__ unsigned smem_u32(const void* p) {
    unsigned r;
    asm("{ .reg .u64 t; cvta.to.shared.u64 t, %1; cvt.u32.u64 %0, t; }" : "=r"(r) : "l"(p));
    return r;
}
__device__ __forceinline__ unsigned mapa_u32(unsigned a, unsigned rnk) {
    unsigned o; asm("mapa.shared::cluster.u32 %0, %1, %2;" : "=r"(o) : "r"(a), "r"(rnk));
    return o;
}
__device__ __forceinline__ void stc(unsigned a, float v) {
    asm volatile("st.shared::cluster.f32 [%0], %1;" :: "r"(a), "f"(v) : "memory");
}
__device__ __forceinline__ void arrive_c(unsigned a) {
    asm volatile("mbarrier.arrive.release.cluster.shared::cluster.b64 _, [%0];"
                 :: "r"(a) : "memory");
}
__device__ __forceinline__ void mbar_init(unsigned a, unsigned c) {
    asm volatile("mbarrier.init.shared.b64 [%0], %1;" :: "r"(a), "r"(c) : "memory");
}
__device__ __forceinline__ void mbar_wait(unsigned a, unsigned par) {
    unsigned done;
    asm volatile("{ .reg .pred p; mbarrier.try_wait.parity.acquire.cluster.shared::cta.b64 p, [%1], %2; selp.b32 %0,1,0,p; }"
                 : "=r"(done) : "r"(a), "r"(par) : "memory");
    while (!done)
        asm volatile("{ .reg .pred p; mbarrier.try_wait.parity.acquire.cluster.shared::cta.b64 p, [%1], %2, 0x989680; selp.b32 %0,1,0,p; }"
                     : "=r"(done) : "r"(a), "r"(par) : "memory");
}
__device__ __forceinline__ unsigned ctarank() {
    unsigned r; asm("mov.u32 %0, %%cluster_ctarank;" : "=r"(r)); return r;
}
#define CLUSTER_SYNC() do { \
    asm volatile("barrier.cluster.arrive.aligned;" ::: "memory"); \
    asm volatile("barrier.cluster.wait.aligned;" ::: "memory"); } while (0)

extern __shared__ float smem_dyn[];

__global__ void pack_kernel(const float* __restrict__ Ww_hh, const float* __restrict__ Wa_hh,
                            const float* __restrict__ W_tag, const float* __restrict__ W_ih,
                            const float* __restrict__ Wa_ih, const float* __restrict__ Ww_ih) {
    int stride = gridDim.x * blockDim.x;
    int t0 = blockIdx.x * blockDim.x + threadIdx.x;
    for (int i = t0; i < G3_*H_; i += stride) {
        int g = i >> 7, d = i & 127;
        g_WwP[(d >> 2)*(G3_*4) + (g << 2) + (d & 3)] = Ww_hh[i];
    }
    for (int i = t0; i < H_*H_; i += stride) {
        int h = i >> 7, d = i & 127;
        g_WaP[(d >> 2)*(H_*4) + (h << 2) + (d & 3)] = Wa_hh[i];
    }
    for (int i = t0; i < NL_*H_; i += stride) {
        int l = i >> 7, h = i & 127;
        g_Wt2[i] = W_tag[l*256 + h] + W_tag[l*256 + 128 + h];
    }
    for (int i = t0; i < DIN_*G3_; i += stride) {
        int g = i / DIN_, d = i - g*DIN_;
        g_WihT[d*G3_ + g] = W_ih[i];
    }
    for (int i = t0; i < DIN_*H_; i += stride) {
        int h = i / DIN_, d = i - h*DIN_;
        g_WaihT[d*H_ + h] = Wa_ih[i];
    }
    for (int i = t0; i < DG_*G3_; i += stride) {
        int g = i / DG_, d = i - g*DG_;
        g_WwihT[d*G3_ + g] = Ww_ih[i];
    }
}

__global__ void __launch_bounds__(384, 1) xw_kernel(
    const int* __restrict__ word, const int* __restrict__ biword,
    const float* __restrict__ wtab, const float* __restrict__ bwtab,
    const float* __restrict__ b_lstm, const float* __restrict__ b_alpha)
{
    __shared__ float sx[16][DIN_];
    int tid = threadIdx.x;
    for (int base = blockIdx.x*16; base < B_*T_; base += gridDim.x*16) {
        for (int t = tid; t < 16*DIN_; t += 384) {
            int it = t / DIN_, d = t - it*DIN_;
            int item = base + it;
            sx[it][d] = (d < DG_) ? wtab[(size_t)word[item]*DG_ + d]
                                  : bwtab[(size_t)biword[item]*DG_ + (d - DG_)];
        }
        __syncthreads();
        int g = tid;
        float acc[16], acca[16];
        #pragma unroll
        for (int it = 0; it < 16; it++) { acc[it] = 0.f; acca[it] = 0.f; }
        for (int d = 0; d < DIN_; d++) {
            float w  = g_WihT[d*G3_ + g];
            float wa = (g < H_) ? g_WaihT[d*H_ + g] : 0.f;
            #pragma unroll
            for (int it = 0; it < 16; it++) {
                float xv = sx[it][d];
                acc[it]  = fmaf(w,  xv, acc[it]);
                acca[it] = fmaf(wa, xv, acca[it]);
            }
        }
        float bl = b_lstm[g];
        for (int it = 0; it < 16; it++) g_xW[(base + it)*G3_ + g] = acc[it] + bl;
        if (g < H_) {
            float ba = b_alpha[g];
            for (int it = 0; it < 16; it++) g_xWa[(base + it)*H_ + g] = acca[it] + ba;
        }
        __syncthreads();
    }
}

__global__ void __launch_bounds__(384, 1) gw_kernel(
    const int* __restrict__ gaz_ids, const int* __restrict__ gaz_mask,
    const float* __restrict__ gtab, const float* __restrict__ b_word)
{
    __shared__ float sg[16][DG_];
    __shared__ int smsk[16];
    int tid = threadIdx.x;
    for (int base = blockIdx.x*16; base < B_*T_*K_; base += gridDim.x*16) {
        if (tid < 16) smsk[tid] = (gaz_mask[base + tid] != 0);
        __syncthreads();
        for (int t = tid; t < 16*DG_; t += 384) {
            int it = t / DG_, d = t - it*DG_;
            sg[it][d] = smsk[it] ? gtab[(size_t)gaz_ids[base + it]*DG_ + d] : 0.f;
        }
        __syncthreads();
        int g = tid;
        float acc[16];
        #pragma unroll
        for (int it = 0; it < 16; it++) acc[it] = 0.f;
        for (int d = 0; d < DG_; d++) {
            float w = g_WwihT[d*G3_ + g];
            #pragma unroll
            for (int it = 0; it < 16; it++) acc[it] = fmaf(w, sg[it][d], acc[it]);
        }
        float bw = b_word[g];
        for (int it = 0; it < 16; it++)
            if (smsk[it]) g_gW[(size_t)(base + it)*G3_ + g] = acc[it] + bw;
        __syncthreads();
    }
}

// 2-CTA cluster per lane: rank0 = owner, rank1 = Ww_hh helper
__global__ void __launch_bounds__(384, 1) __cluster_dims__(2, 1, 1) rec_kernel(
    const float* __restrict__ W_hh,
    const int* __restrict__ gmask, const int* __restrict__ gstart)
{
    float* sm = smem_dyn;
    int tid = threadIdx.x;
    unsigned rank = ctarank();
    int b = blockIdx.x >> 1;
    unsigned sb = smem_u32(sm);

    if (rank == 0) {
        for (int i = tid; i < G3_*H_; i += 384) {
            int g = i >> 7, d = i & 127;
            sm[O_SW + (d >> 2)*(G3_*4) + (g << 2) + (d & 3)] = __ldg(&W_hh[i]);
        }
    } else {
        for (int i = tid; i < G3_*H_; i += 384) sm[O_SW + i] = g_WwP[i];
    }
    for (int i = tid; i < 3072 + 1024 + 1024; i += 384) sm[O_VH + i] = 0.f;
    if (tid == 0) { mbar_init(sb + O_MBAR*4, 12); mbar_init(sb + O_MBAR*4 + 8, 4); }
    __syncthreads();
    CLUSTER_SYNC();

    if (rank == 1) {
        // ---------------- helper: vh = Ww_hh @ h(j-1), push to owner ----------------
        const float4* sW4 = (const float4*)(sm + O_SW);
        const float4* hm4 = (const float4*)(sm + O_HR);
        unsigned r_vh = mapa_u32(sb + (O_VH + tid)*4, 0u);
        unsigned r_mb = mapa_u32(sb + O_MBAR*4, 0u);
        unsigned ph = 0;
        for (int j = 0; j < T_; j++) {
            if (j > 0) { mbar_wait(sb + O_MBAR*4 + 8, ph); ph ^= 1; }
            int pslot = (j + 7) & 7;
            float a0 = 0.f, a1 = 0.f;
            #pragma unroll
            for (int c = 0; c < 32; c++) {
                float4 w = sW4[c*G3_ + tid];
                float4 hh = hm4[c];
                a0 = fmaf(w.x, hh.x, fmaf(w.y, hh.y, a0));
                a1 = fmaf(w.z, hh.z, fmaf(w.w, hh.w, a1));
            }
            stc(r_vh + (unsigned)pslot*1536u, a0 + a1);
            __syncwarp();
            if ((tid & 31) == 0) arrive_c(r_mb);
        }
        CLUSTER_SYNC();
        return;
    }

    // ---------------- owner ----------------
    float* vhring = sm + O_VH;
    float* hring  = sm + O_HR;
    float* cring  = sm + O_CR;
    float* i_s    = sm + O_IS;
    float* o_s    = sm + O_OS;
    float* gt_s   = sm + O_GT;
    float* cw     = sm + O_CW;
    float* part   = sm + O_PART;
    int*   si     = (int*)(sm + O_INT);
    int* act_k  = si;
    int* act_s  = si + 8;
    int* p_nact = si + 16;
    int* p_hw   = si + 17;

    const float4* WaP = (const float4*)g_WaP;
    const float4* sW4 = (const float4*)(sm + O_SW);
    const float4* cw4 = (const float4*)cw;
    unsigned r_hm = (tid < 128) ? mapa_u32(sb + (O_HR + tid)*4, 1u) : 0u;
    unsigned r_hb = mapa_u32(sb + O_MBAR*4 + 8, 1u);

    float acc[8];
    int h = tid & 127;
    int p = tid >> 7;
    unsigned pv = 0;

    for (int j = 0; j < T_; j++) {
        int pslot = (j + 7) & 7;
        float xwa_r = (tid < 128) ? __ldg(&g_xWa[(b*T_ + j)*H_ + h]) : 0.f;

        // Stage A: gates from xW + W_hh@h_prev ; edge compaction ; L2 prefetches
        {
            int g = tid;
            const float4* hp4 = (const float4*)(hring + pslot*H_);
            float a1x = 0.f, a1y = 0.f;
            #pragma unroll
            for (int c = 0; c < 32; c++) {
                float4 w1 = sW4[c*G3_ + g];
                float4 hh = hp4[c];
                a1x = fmaf(w1.x, hh.x, fmaf(w1.y, hh.y, a1x));
                a1y = fmaf(w1.z, hh.z, fmaf(w1.w, hh.w, a1y));
            }
            float gv = g_xW[(b*T_ + j)*G3_ + g] + a1x + a1y;
            if (g < 128)      i_s[g]        = 1.f / (1.f + expf(-gv));
            else if (g < 256) o_s[g - 128]  = 1.f / (1.f + expf(-gv));
            else              gt_s[g - 256] = tanhf(gv);

            if (tid >= 352) {
                int lane = tid - 352;
                int m = 0, s = 0;
                if (lane < 8) {
                    int idx = (b*T_ + j)*K_ + lane;
                    m = (gmask[idx] != 0);
                    s = gstart[idx];
                }
                unsigned bal = __ballot_sync(0xffffffffu, m != 0);
                if (lane < 8 && m) {
                    int pos = __popc(bal & ((1u << lane) - 1u));
                    act_k[pos] = lane;
                    act_s[pos] = s;
                    // prefetch this edge's gW row into L2 (consumed in stage B)
                    const char* pgw = (const char*)(g_gW + (size_t)((b*T_ + j)*K_ + lane)*G3_);
                    #pragma unroll
                    for (int q = 0; q < 12; q++)
                        asm volatile("prefetch.global.L2 [%0];" :: "l"(pgw + q*128));
                }
                if (lane == 0) { *p_nact = __popc(bal); *p_hw = bal ? 1 : 0; }
                // prefetch next step's xW / xWa rows
                if (j + 1 < T_) {
                    if (lane >= 8 && lane < 20) {
                        const char* px = (const char*)(g_xW + (size_t)(b*T_ + j + 1)*G3_);
                        asm volatile("prefetch.global.L2 [%0];" :: "l"(px + (lane - 8)*128));
                    } else if (lane >= 20 && lane < 24) {
                        const char* pa = (const char*)(g_xWa + (size_t)(b*T_ + j + 1)*H_);
                        asm volatile("prefetch.global.L2 [%0];" :: "l"(pa + (lane - 20)*128));
                    }
                }
            }
        }
        mbar_wait(sb + O_MBAR*4, pv); pv ^= 1;    // vh(j-1) arrived
        __syncthreads();
        int nact = *p_nact;
        int nr = (nact + 3) & ~3;

        // hoist first half of stage-C weights (L2 latency overlaps stage B)
        float4 w0[8];
        if (nact > 0 && p < 2) {
            #pragma unroll
            for (int cc = 0; cc < 8; cc++)
                w0[cc] = WaP[((p << 4) + cc)*H_ + h];
        }

        // Stage B: word cells (3 edges per pass across p-groups) + zero-pad
        for (int base = 0; base < nact; base += 3) {
            int kk = base + p;
            if (kk < nact) {
                int k = act_k[kk], s = act_s[kk], slot = s & 7;
                const float* gw = g_gW + (size_t)((b*T_ + j)*K_ + k)*G3_;
                float iw = gw[h]       + vhring[slot*G3_ + h];
                float fw = gw[128 + h] + vhring[slot*G3_ + 128 + h];
                float gg = gw[256 + h] + vhring[slot*G3_ + 256 + h];
                float cs = cring[slot*H_ + h];
                float sf  = 1.f / (1.f + expf(-fw));
                float siw = 1.f / (1.f + expf(-iw));
                cw[kk*H_ + h] = fmaf(sf, cs, siw * tanhf(gg));
            }
        }
        { int kkz = nact + p; if (kkz < nr) cw[kkz*H_ + h] = 0.f; }
        __syncthreads();

        // Stage C: Wa_hh@c_w, d-range split over p in {0,1}; w0 preloaded
        if (nact > 0 && p < 2) {
            float4 w1[8];
            #pragma unroll
            for (int cc = 0; cc < 8; cc++)
                w1[cc] = WaP[((p << 4) + 8 + cc)*H_ + h];
            #pragma unroll
            for (int r = 0; r < 8; r++) acc[r] = 0.f;
            #pragma unroll
            for (int cc = 0; cc < 8; cc++) {
                int c = (p << 4) + cc;
                #pragma unroll
                for (int r = 0; r < 8; r++) {
                    if (r < nr) {
                        float4 cv = cw4[r*32 + c];
                        acc[r] = fmaf(w0[cc].x, cv.x, fmaf(w0[cc].y, cv.y,
                                 fmaf(w0[cc].z, cv.z, fmaf(w0[cc].w, cv.w, acc[r]))));
                    }
                }
            }
            #pragma unroll
            for (int cc = 0; cc < 8; cc++) {
                int c = (p << 4) + 8 + cc;
                #pragma unroll
                for (int r = 0; r < 8; r++) {
                    if (r < nr) {
                        float4 cv = cw4[r*32 + c];
                        acc[r] = fmaf(w1[cc].x, cv.x, fmaf(w1[cc].y, cv.y,
                                 fmaf(w1[cc].z, cv.z, fmaf(w1[cc].w, cv.w, acc[r]))));
                    }
                }
            }
            if (p == 1) {
                #pragma unroll
                for (int r = 0; r < 8; r++)
                    if (r < nact) part[r*H_ + h] = acc[r];
            }
        }
        __syncthreads();

        // Stage D: alpha aggregate, state update, h out (global + helper mirror)
        if (tid < 128) {
            float num = 0.f, den = 0.f;
            if (nact > 0) {
                #pragma unroll
                for (int r = 0; r < 8; r++) {
                    if (r < nact) {
                        float dotv = acc[r] + part[r*H_ + h];
                        float al = 1.f / (1.f + expf(-(xwa_r + dotv)));
                        float e = expf(al);
                        num = fmaf(e, cw[r*H_ + h], num);
                        den += e;
                    }
                }
            }
            float ii = i_s[h], oo = o_s[h], gg = gt_s[h];
            float cprev = cring[pslot*H_ + h];
            float cnew;
            if (*p_hw) { float wc = expf(ii); cnew = (wc*gg + num) / (wc + den); }
            else       cnew = fmaf(ii, gg, (1.f - ii)*cprev);
            float hnew = oo * tanhf(cnew);
            hring[(j & 7)*H_ + h] = hnew;
            cring[(j & 7)*H_ + h] = cnew;
            g_hout[((size_t)b*T_ + j)*H_ + h] = hnew;
            if (j < T_ - 1) {
                stc(r_hm, hnew);
                __syncwarp();
                if ((tid & 31) == 0) arrive_c(r_hb);
            }
        }
        __syncthreads();
    }
    CLUSTER_SYNC();
}

// ---------------- tag post-pass: logits + argmax, fully parallel ----------------
__global__ void __launch_bounds__(160, 8) tag_kernel(
    const float* __restrict__ b_tag, const int* __restrict__ mask, float* __restrict__ out)
{
    __shared__ float sh[H_];
    __shared__ float sp[160];
    int pos = blockIdx.x, t = threadIdx.x;
    if (t < 128) sh[t] = g_hout[(size_t)pos*H_ + t];
    __syncthreads();
    {
        int l = t >> 3, seg = t & 7;
        const float* w = g_Wt2 + l*H_ + seg*16;
        float a = 0.f;
        #pragma unroll
        for (int q = 0; q < 16; q++) a = fmaf(w[q], sh[seg*16 + q], a);
        sp[t] = a;
    }
    __syncthreads();
    if (t < 32) {
        float v = -3.4e38f;
        if (t < NL_) {
            float s = __ldg(&b_tag[t]);
            #pragma unroll
            for (int q = 0; q < 8; q++) s += sp[t*8 + q];
            v = s;
        }
        int bi = t;
        #pragma unroll
        for (int off = 16; off; off >>= 1) {
            float ov = __shfl_xor_sync(0xffffffffu, v, off);
            int   oi = __shfl_xor_sync(0xffffffffu, bi, off);
            if (ov > v || (ov == v && oi < bi)) { v = ov; bi = oi; }
        }
        if (t == 0) out[pos] = (float)(mask[pos] * bi);
    }
}

extern "C" void kernel_launch(void* const* d_in, const int* in_sizes, int n_in,
                              void* d_out, int out_size) {
    const int*   word       = (const int*)d_in[0];
    const int*   biword     = (const int*)d_in[1];
    const int*   gaz_ids    = (const int*)d_in[2];
    const int*   gaz_starts = (const int*)d_in[3];
    const int*   gaz_mask   = (const int*)d_in[4];
    const int*   mask       = (const int*)d_in[5];
    const float* wtab       = (const float*)d_in[6];
    const float* bwtab      = (const float*)d_in[7];
    const float* gtab       = (const float*)d_in[8];
    const float* W_ih       = (const float*)d_in[9];
    const float* W_hh       = (const float*)d_in[10];
    const float* b_lstm     = (const float*)d_in[11];
    const float* Wa_ih      = (const float*)d_in[12];
    const float* Wa_hh      = (const float*)d_in[13];
    const float* b_alpha    = (const float*)d_in[14];
    const float* Ww_ih      = (const float*)d_in[15];
    const float* Ww_hh      = (const float*)d_in[16];
    const float* b_word     = (const float*)d_in[17];
    const float* W_tag      = (const float*)d_in[18];
    const float* b_tag      = (const float*)d_in[19];

    cudaFuncSetAttribute(rec_kernel, cudaFuncAttributeMaxDynamicSharedMemorySize, REC_SMEM);

    pack_kernel<<<64, 256>>>(Ww_hh, Wa_hh, W_tag, W_ih, Wa_ih, Ww_ih);
    xw_kernel<<<256, 384>>>(word, biword, wtab, bwtab, b_lstm, b_alpha);
    gw_kernel<<<256, 384>>>(gaz_ids, gaz_mask, gtab, b_word);
    rec_kernel<<<16, 384, REC_SMEM>>>(W_hh, gaz_mask, gaz_starts);
    tag_kernel<<<B_*T_, 160>>>(b_tag, mask, (float*)d_out);
}

// round 17
// speedup vs baseline: 1.3908x; 1.3908x over previous
#include <cuda_runtime.h>
#include <cstddef>

#define B_   8
#define T_   512
#define K_   8
#define H_   128
#define G3_  384
#define DIN_ 100
#define DG_  50
#define NL_  20

// device scratch (no allocation allowed)
__device__ __align__(16) float g_xW  [B_*T_*G3_];
__device__ __align__(16) float g_xWa [B_*T_*H_];
__device__ __align__(16) float g_gW  [B_*T_*K_*G3_];
__device__ __align__(16) float g_WwP [32*G3_*4];   // Ww_hh packed [d/4][g][4]
__device__ __align__(16) float g_WaP [32*H_*4];    // Wa_hh packed [d/4][h][4]
__device__ __align__(16) float g_Wt2 [NL_*H_];     // W_tag[:, :128] + W_tag[:, 128:]
__device__ __align__(16) float g_WihT [DIN_*G3_];
__device__ __align__(16) float g_WaihT[DIN_*H_];
__device__ __align__(16) float g_WwihT[DG_*G3_];
__device__ __align__(16) float g_hout[B_*T_*H_];   // h history for tag post-pass

// smem layout (float offsets); helper reuses O_HR as its h mirror
#define O_SW    0
#define O_VH    49152
#define O_HR    52224
#define O_CR    53248
#define O_IS    54272
#define O_OS    54400
#define O_GT    54528
#define O_CW    54656
#define O_PART  55680
#define O_INT   56704
#define O_MBAR  56736      // mbar0 (vh, count 12) @ +0 ; mbar1 (h, count 4) @ +8B
#define REC_SMEM ((56740) * 4)

__device__ __forceinline__ unsigned smem_u32(const void* p) {
    unsigned r;
    asm("{ .reg .u64 t; cvta.to.shared.u64 t, %1; cvt.u32.u64 %0, t; }" : "=r"(r) : "l"(p));
    return r;
}
__device__ __forceinline__ unsigned mapa_u32(unsigned a, unsigned rnk) {
    unsigned o; asm("mapa.shared::cluster.u32 %0, %1, %2;" : "=r"(o) : "r"(a), "r"(rnk));
    return o;
}
__device__ __forceinline__ void stc(unsigned a, float v) {
    asm volatile("st.shared::cluster.f32 [%0], %1;" :: "r"(a), "f"(v) : "memory");
}
__device__ __forceinline__ void arrive_c(unsigned a) {
    asm volatile("mbarrier.arrive.release.cluster.shared::cluster.b64 _, [%0];"
                 :: "r"(a) : "memory");
}
__device__ __forceinline__ void mbar_init(unsigned a, unsigned c) {
    asm volatile("mbarrier.init.shared.b64 [%0], %1;" :: "r"(a), "r"(c) : "memory");
}
__device__ __forceinline__ void mbar_wait(unsigned a, unsigned par) {
    unsigned done;
    asm volatile("{ .reg .pred p; mbarrier.try_wait.parity.acquire.cluster.shared::cta.b64 p, [%1], %2; selp.b32 %0,1,0,p; }"
                 : "=r"(done) : "r"(a), "r"(par) : "memory");
    while (!done)
        asm volatile("{ .reg .pred p; mbarrier.try_wait.parity.acquire.cluster.shared::cta.b64 p, [%1], %2, 0x989680; selp.b32 %0,1,0,p; }"
                     : "=r"(done) : "r"(a), "r"(par) : "memory");
}
__device__ __forceinline__ unsigned ctarank() {
    unsigned r; asm("mov.u32 %0, %%cluster_ctarank;" : "=r"(r)); return r;
}
#define CLUSTER_SYNC() do { \
    asm volatile("barrier.cluster.arrive.aligned;" ::: "memory"); \
    asm volatile("barrier.cluster.wait.aligned;" ::: "memory"); } while (0)

extern __shared__ float smem_dyn[];

__global__ void pack_kernel(const float* __restrict__ Ww_hh, const float* __restrict__ Wa_hh,
                            const float* __restrict__ W_tag, const float* __restrict__ W_ih,
                            const float* __restrict__ Wa_ih, const float* __restrict__ Ww_ih) {
    int stride = gridDim.x * blockDim.x;
    int t0 = blockIdx.x * blockDim.x + threadIdx.x;
    for (int i = t0; i < G3_*H_; i += stride) {
        int g = i >> 7, d = i & 127;
        g_WwP[(d >> 2)*(G3_*4) + (g << 2) + (d & 3)] = Ww_hh[i];
    }
    for (int i = t0; i < H_*H_; i += stride) {
        int h = i >> 7, d = i & 127;
        g_WaP[(d >> 2)*(H_*4) + (h << 2) + (d & 3)] = Wa_hh[i];
    }
    for (int i = t0; i < NL_*H_; i += stride) {
        int l = i >> 7, h = i & 127;
        g_Wt2[i] = W_tag[l*256 + h] + W_tag[l*256 + 128 + h];
    }
    for (int i = t0; i < DIN_*G3_; i += stride) {
        int g = i / DIN_, d = i - g*DIN_;
        g_WihT[d*G3_ + g] = W_ih[i];
    }
    for (int i = t0; i < DIN_*H_; i += stride) {
        int h = i / DIN_, d = i - h*DIN_;
        g_WaihT[d*H_ + h] = Wa_ih[i];
    }
    for (int i = t0; i < DG_*G3_; i += stride) {
        int g = i / DG_, d = i - g*DG_;
        g_WwihT[d*G3_ + g] = Ww_ih[i];
    }
}

__global__ void __launch_bounds__(384, 1) xw_kernel(
    const int* __restrict__ word, const int* __restrict__ biword,
    const float* __restrict__ wtab, const float* __restrict__ bwtab,
    const float* __restrict__ b_lstm, const float* __restrict__ b_alpha)
{
    __shared__ float sx[16][DIN_];
    int tid = threadIdx.x;
    for (int base = blockIdx.x*16; base < B_*T_; base += gridDim.x*16) {
        for (int t = tid; t < 16*DIN_; t += 384) {
            int it = t / DIN_, d = t - it*DIN_;
            int item = base + it;
            sx[it][d] = (d < DG_) ? wtab[(size_t)word[item]*DG_ + d]
                                  : bwtab[(size_t)biword[item]*DG_ + (d - DG_)];
        }
        __syncthreads();
        int g = tid;
        float acc[16], acca[16];
        #pragma unroll
        for (int it = 0; it < 16; it++) { acc[it] = 0.f; acca[it] = 0.f; }
        for (int d = 0; d < DIN_; d++) {
            float w  = g_WihT[d*G3_ + g];
            float wa = (g < H_) ? g_WaihT[d*H_ + g] : 0.f;
            #pragma unroll
            for (int it = 0; it < 16; it++) {
                float xv = sx[it][d];
                acc[it]  = fmaf(w,  xv, acc[it]);
                acca[it] = fmaf(wa, xv, acca[it]);
            }
        }
        float bl = b_lstm[g];
        for (int it = 0; it < 16; it++) g_xW[(base + it)*G3_ + g] = acc[it] + bl;
        if (g < H_) {
            float ba = b_alpha[g];
            for (int it = 0; it < 16; it++) g_xWa[(base + it)*H_ + g] = acca[it] + ba;
        }
        __syncthreads();
    }
}

__global__ void __launch_bounds__(384, 1) gw_kernel(
    const int* __restrict__ gaz_ids, const int* __restrict__ gaz_mask,
    const float* __restrict__ gtab, const float* __restrict__ b_word)
{
    __shared__ float sg[16][DG_];
    __shared__ int smsk[16];
    int tid = threadIdx.x;
    for (int base = blockIdx.x*16; base < B_*T_*K_; base += gridDim.x*16) {
        if (tid < 16) smsk[tid] = (gaz_mask[base + tid] != 0);
        __syncthreads();
        for (int t = tid; t < 16*DG_; t += 384) {
            int it = t / DG_, d = t - it*DG_;
            sg[it][d] = smsk[it] ? gtab[(size_t)gaz_ids[base + it]*DG_ + d] : 0.f;
        }
        __syncthreads();
        int g = tid;
        float acc[16];
        #pragma unroll
        for (int it = 0; it < 16; it++) acc[it] = 0.f;
        for (int d = 0; d < DG_; d++) {
            float w = g_WwihT[d*G3_ + g];
            #pragma unroll
            for (int it = 0; it < 16; it++) acc[it] = fmaf(w, sg[it][d], acc[it]);
        }
        float bw = b_word[g];
        for (int it = 0; it < 16; it++)
            if (smsk[it]) g_gW[(size_t)(base + it)*G3_ + g] = acc[it] + bw;
        __syncthreads();
    }
}

// 2-CTA cluster per lane: rank0 = owner, rank1 = Ww_hh helper
__global__ void __launch_bounds__(384, 1) __cluster_dims__(2, 1, 1) rec_kernel(
    const float* __restrict__ W_hh,
    const int* __restrict__ gmask, const int* __restrict__ gstart)
{
    float* sm = smem_dyn;
    int tid = threadIdx.x;
    unsigned rank = ctarank();
    int b = blockIdx.x >> 1;
    unsigned sb = smem_u32(sm);

    if (rank == 0) {
        for (int i = tid; i < G3_*H_; i += 384) {
            int g = i >> 7, d = i & 127;
            sm[O_SW + (d >> 2)*(G3_*4) + (g << 2) + (d & 3)] = __ldg(&W_hh[i]);
        }
    } else {
        for (int i = tid; i < G3_*H_; i += 384) sm[O_SW + i] = g_WwP[i];
    }
    for (int i = tid; i < 3072 + 1024 + 1024; i += 384) sm[O_VH + i] = 0.f;
    if (tid == 0) { mbar_init(sb + O_MBAR*4, 12); mbar_init(sb + O_MBAR*4 + 8, 4); }
    __syncthreads();
    CLUSTER_SYNC();

    if (rank == 1) {
        // ---------------- helper: vh = Ww_hh @ h(j-1), push to owner ----------------
        const float4* sW4 = (const float4*)(sm + O_SW);
        const float4* hm4 = (const float4*)(sm + O_HR);
        unsigned r_vh = mapa_u32(sb + (O_VH + tid)*4, 0u);
        unsigned r_mb = mapa_u32(sb + O_MBAR*4, 0u);
        unsigned ph = 0;
        for (int j = 0; j < T_; j++) {
            if (j > 0) { mbar_wait(sb + O_MBAR*4 + 8, ph); ph ^= 1; }
            int pslot = (j + 7) & 7;
            float a0 = 0.f, a1 = 0.f;
            #pragma unroll
            for (int c = 0; c < 32; c++) {
                float4 w = sW4[c*G3_ + tid];
                float4 hh = hm4[c];
                a0 = fmaf(w.x, hh.x, fmaf(w.y, hh.y, a0));
                a1 = fmaf(w.z, hh.z, fmaf(w.w, hh.w, a1));
            }
            stc(r_vh + (unsigned)pslot*1536u, a0 + a1);
            __syncwarp();
            if ((tid & 31) == 0) arrive_c(r_mb);
        }
        CLUSTER_SYNC();
        return;
    }

    // ---------------- owner ----------------
    float* vhring = sm + O_VH;
    float* hring  = sm + O_HR;
    float* cring  = sm + O_CR;
    float* i_s    = sm + O_IS;
    float* o_s    = sm + O_OS;
    float* gt_s   = sm + O_GT;
    float* cw     = sm + O_CW;
    float* part   = sm + O_PART;
    int*   si     = (int*)(sm + O_INT);
    int* act_k  = si;
    int* act_s  = si + 8;
    int* p_nact = si + 16;
    int* p_hw   = si + 17;

    const float4* WaP = (const float4*)g_WaP;
    const float4* sW4 = (const float4*)(sm + O_SW);
    const float4* cw4 = (const float4*)cw;
    unsigned r_hm = (tid < 128) ? mapa_u32(sb + (O_HR + tid)*4, 1u) : 0u;
    unsigned r_hb = mapa_u32(sb + O_MBAR*4 + 8, 1u);

    float acc[8];
    int h = tid & 127;
    int p = tid >> 7;
    unsigned pv = 0;

    for (int j = 0; j < T_; j++) {
        int pslot = (j + 7) & 7;
        float xwa_r = (tid < 128) ? __ldg(&g_xWa[(b*T_ + j)*H_ + h]) : 0.f;

        // Stage A: gates from xW + W_hh@h_prev ; edge compaction
        {
            int g = tid;
            const float4* hp4 = (const float4*)(hring + pslot*H_);
            float a1x = 0.f, a1y = 0.f;
            #pragma unroll
            for (int c = 0; c < 32; c++) {
                float4 w1 = sW4[c*G3_ + g];
                float4 hh = hp4[c];
                a1x = fmaf(w1.x, hh.x, fmaf(w1.y, hh.y, a1x));
                a1y = fmaf(w1.z, hh.z, fmaf(w1.w, hh.w, a1y));
            }
            float gv = g_xW[(b*T_ + j)*G3_ + g] + a1x + a1y;
            if (g < 128)      i_s[g]        = 1.f / (1.f + expf(-gv));
            else if (g < 256) o_s[g - 128]  = 1.f / (1.f + expf(-gv));
            else              gt_s[g - 256] = tanhf(gv);

            if (tid >= 352) {
                int lane = tid - 352;
                int m = 0, s = 0;
                if (lane < 8) {
                    int idx = (b*T_ + j)*K_ + lane;
                    m = (gmask[idx] != 0);
                    s = gstart[idx];
                }
                unsigned bal = __ballot_sync(0xffffffffu, m != 0);
                if (lane < 8 && m) {
                    int pos = __popc(bal & ((1u << lane) - 1u));
                    act_k[pos] = lane;
                    act_s[pos] = s;
                }
                if (lane == 0) { *p_nact = __popc(bal); *p_hw = bal ? 1 : 0; }
            }
        }
        mbar_wait(sb + O_MBAR*4, pv); pv ^= 1;    // vh(j-1) arrived
        __syncthreads();
        int nact = *p_nact;
        int nr = (nact + 3) & ~3;

        // Stage B: word cells — split load/compute phases, batched LDGs (MLP up to 9)
        {
            float iw[3], fw[3], gg[3], cs[3];
            int slt[3];
            #pragma unroll
            for (int q = 0; q < 3; q++) {
                int kk = q*3 + p;
                if (kk < nact) {
                    int k = act_k[kk];
                    slt[q] = act_s[kk] & 7;
                    const float* gw = g_gW + (size_t)((b*T_ + j)*K_ + k)*G3_;
                    iw[q] = gw[h];
                    fw[q] = gw[128 + h];
                    gg[q] = gw[256 + h];
                    cs[q] = cring[slt[q]*H_ + h];
                }
            }
            #pragma unroll
            for (int q = 0; q < 3; q++) {
                int kk = q*3 + p;
                if (kk < nact) {
                    float iw2 = iw[q] + vhring[slt[q]*G3_ + h];
                    float fw2 = fw[q] + vhring[slt[q]*G3_ + 128 + h];
                    float gg2 = gg[q] + vhring[slt[q]*G3_ + 256 + h];
                    float sf  = 1.f / (1.f + expf(-fw2));
                    float siw = 1.f / (1.f + expf(-iw2));
                    cw[kk*H_ + h] = fmaf(sf, cs[q], siw * tanhf(gg2));
                }
            }
            int kkz = nact + p;
            if (kkz < nr) cw[kkz*H_ + h] = 0.f;
        }
        __syncthreads();

        // Stage C: Wa_hh@c_w, d-range split over p in {0,1}
        if (nact > 0 && p < 2) {
            #pragma unroll
            for (int r = 0; r < 8; r++) acc[r] = 0.f;
            #pragma unroll 4
            for (int cc = 0; cc < 16; cc++) {
                int c = (p << 4) + cc;
                float4 w = WaP[c*H_ + h];
                #pragma unroll
                for (int r = 0; r < 8; r++) {
                    if (r < nr) {
                        float4 cv = cw4[r*32 + c];
                        acc[r] = fmaf(w.x, cv.x, fmaf(w.y, cv.y,
                                 fmaf(w.z, cv.z, fmaf(w.w, cv.w, acc[r]))));
                    }
                }
            }
            if (p == 1) {
                #pragma unroll
                for (int r = 0; r < 8; r++)
                    if (r < nact) part[r*H_ + h] = acc[r];
            }
        }
        __syncthreads();

        // Stage D: alpha aggregate, state update, h out (global + helper mirror)
        if (tid < 128) {
            float num = 0.f, den = 0.f;
            if (nact > 0) {
                #pragma unroll
                for (int r = 0; r < 8; r++) {
                    if (r < nact) {
                        float dotv = acc[r] + part[r*H_ + h];
                        float al = 1.f / (1.f + expf(-(xwa_r + dotv)));
                        float e = expf(al);
                        num = fmaf(e, cw[r*H_ + h], num);
                        den += e;
                    }
                }
            }
            float ii = i_s[h], oo = o_s[h], gg = gt_s[h];
            float cprev = cring[pslot*H_ + h];
            float cnew;
            if (*p_hw) { float wc = expf(ii); cnew = (wc*gg + num) / (wc + den); }
            else       cnew = fmaf(ii, gg, (1.f - ii)*cprev);
            float hnew = oo * tanhf(cnew);
            hring[(j & 7)*H_ + h] = hnew;
            cring[(j & 7)*H_ + h] = cnew;
            g_hout[((size_t)b*T_ + j)*H_ + h] = hnew;
            if (j < T_ - 1) {
                stc(r_hm, hnew);
                __syncwarp();
                if ((tid & 31) == 0) arrive_c(r_hb);
            }
        }
        __syncthreads();
    }
    CLUSTER_SYNC();
}

// ---------------- tag post-pass: logits + argmax, fully parallel ----------------
__global__ void __launch_bounds__(160, 8) tag_kernel(
    const float* __restrict__ b_tag, const int* __restrict__ mask, float* __restrict__ out)
{
    __shared__ float sh[H_];
    __shared__ float sp[160];
    int pos = blockIdx.x, t = threadIdx.x;
    if (t < 128) sh[t] = g_hout[(size_t)pos*H_ + t];
    __syncthreads();
    {
        int l = t >> 3, seg = t & 7;
        const float* w = g_Wt2 + l*H_ + seg*16;
        float a = 0.f;
        #pragma unroll
        for (int q = 0; q < 16; q++) a = fmaf(w[q], sh[seg*16 + q], a);
        sp[t] = a;
    }
    __syncthreads();
    if (t < 32) {
        float v = -3.4e38f;
        if (t < NL_) {
            float s = __ldg(&b_tag[t]);
            #pragma unroll
            for (int q = 0; q < 8; q++) s += sp[t*8 + q];
            v = s;
        }
        int bi = t;
        #pragma unroll
        for (int off = 16; off; off >>= 1) {
            float ov = __shfl_xor_sync(0xffffffffu, v, off);
            int   oi = __shfl_xor_sync(0xffffffffu, bi, off);
            if (ov > v || (ov == v && oi < bi)) { v = ov; bi = oi; }
        }
        if (t == 0) out[pos] = (float)(mask[pos] * bi);
    }
}

extern "C" void kernel_launch(void* const* d_in, const int* in_sizes, int n_in,
                              void* d_out, int out_size) {
    const int*   word       = (const int*)d_in[0];
    const int*   biword     = (const int*)d_in[1];
    const int*   gaz_ids    = (const int*)d_in[2];
    const int*   gaz_starts = (const int*)d_in[3];
    const int*   gaz_mask   = (const int*)d_in[4];
    const int*   mask       = (const int*)d_in[5];
    const float* wtab       = (const float*)d_in[6];
    const float* bwtab      = (const float*)d_in[7];
    const float* gtab       = (const float*)d_in[8];
    const float* W_ih       = (const float*)d_in[9];
    const float* W_hh       = (const float*)d_in[10];
    const float* b_lstm     = (const float*)d_in[11];
    const float* Wa_ih      = (const float*)d_in[12];
    const float* Wa_hh      = (const float*)d_in[13];
    const float* b_alpha    = (const float*)d_in[14];
    const float* Ww_ih      = (const float*)d_in[15];
    const float* Ww_hh      = (const float*)d_in[16];
    const float* b_word     = (const float*)d_in[17];
    const float* W_tag      = (const float*)d_in[18];
    const float* b_tag      = (const float*)d_in[19];

    cudaFuncSetAttribute(rec_kernel, cudaFuncAttributeMaxDynamicSharedMemorySize, REC_SMEM);

    pack_kernel<<<64, 256>>>(Ww_hh, Wa_hh, W_tag, W_ih, Wa_ih, Ww_ih);
    xw_kernel<<<256, 384>>>(word, biword, wtab, bwtab, b_lstm, b_alpha);
    gw_kernel<<<256, 384>>>(gaz_ids, gaz_mask, gtab, b_word);
    rec_kernel<<<16, 384, REC_SMEM>>>(W_hh, gaz_mask, gaz_starts);
    tag_kernel<<<B_*T_, 160>>>(b_tag, mask, (float*)d_out);
}